// round 2
// baseline (speedup 1.0000x reference)
#include <cuda_runtime.h>
#include <math.h>

// ---------------- Problem constants ----------------
#define BB 4
#define TT 1024
#define DD 512
#define LL 4
#define NN 16
#define DC 4
#define DI 1024
#define DTR 32
#define HH 128
#define EPSV 1e-5f

#define MROWS (BB*TT)   // 4096

// ---------------- Scratch (device globals; no allocs allowed) ----------------
__device__ float g_x[MROWS * DD];        // running residual stream x
__device__ float g_xz[MROWS * 2 * DI];   // in_proj output (x_in | z)
__device__ float g_xc[MROWS * DI];       // conv+silu output
__device__ float g_dbc[MROWS * 64];      // x_proj output (dt_r | B | C)
__device__ float g_dt[MROWS * DI];       // softplus(dt)
__device__ float g_y[MROWS * DI];        // scan output (gated)
__device__ float g_out[MROWS * DD];      // out_proj output
__device__ float g_pooled[BB * DD];      // attention-pooled

// ---------------- Helpers ----------------
__device__ __forceinline__ float silu_fast(float a) {
    return a * (1.0f / (1.0f + __expf(-a)));
}

template<int WARPS>
__device__ __forceinline__ float block_sum(float v, float* red) {
    #pragma unroll
    for (int o = 16; o; o >>= 1) v += __shfl_xor_sync(0xffffffffu, v, o);
    int w = threadIdx.x >> 5;
    if ((threadIdx.x & 31) == 0) red[w] = v;
    __syncthreads();
    float s = 0.f;
    #pragma unroll
    for (int i = 0; i < WARPS; i++) s += red[i];
    __syncthreads();
    return s;
}

template<int WARPS>
__device__ __forceinline__ float block_max(float v, float* red) {
    #pragma unroll
    for (int o = 16; o; o >>= 1) v = fmaxf(v, __shfl_xor_sync(0xffffffffu, v, o));
    int w = threadIdx.x >> 5;
    if ((threadIdx.x & 31) == 0) red[w] = v;
    __syncthreads();
    float s = -1e30f;
    #pragma unroll
    for (int i = 0; i < WARPS; i++) s = fmaxf(s, red[i]);
    __syncthreads();
    return s;
}

// ---------------- Copy input into residual stream ----------------
__global__ void copy_kernel(const float* __restrict__ src, int n) {
    int i = blockIdx.x * blockDim.x + threadIdx.x;
    if (i < n) g_x[i] = src[i];
}

// ---------------- Generic tiled SGEMM: C[M,N] = A[M,K(lda)] @ W[N,K]^T ----------------
// ACT: 0 = none, 1 = softplus(acc + bias[n])
template<int BM, int BN, int BK, int TM, int TN, int ACT>
__global__ void gemm_tn(const float* __restrict__ A, int lda,
                        const float* __restrict__ W,
                        const float* __restrict__ bias,
                        float* __restrict__ C,
                        int M, int N, int K) {
    constexpr int THREADS = (BM / TM) * (BN / TN);
    __shared__ float As[BK][BM + 4];
    __shared__ float Bs[BK][BN + 4];

    const int tid = threadIdx.x;
    const int tx = tid % (BN / TN);
    const int ty = tid / (BN / TN);
    const int m0 = blockIdx.y * BM;
    const int n0 = blockIdx.x * BN;

    float acc[TM][TN];
    #pragma unroll
    for (int i = 0; i < TM; i++)
        #pragma unroll
        for (int j = 0; j < TN; j++) acc[i][j] = 0.f;

    float ar[TM], br[TN];

    for (int k0 = 0; k0 < K; k0 += BK) {
        // Load A tile (BM x BK) -> As[k][m]
        constexpr int A_LD4 = BM * BK / 4;
        #pragma unroll
        for (int i = tid; i < A_LD4; i += THREADS) {
            int row = i / (BK / 4);
            int c4  = i % (BK / 4);
            float4 v = *(const float4*)&A[(size_t)(m0 + row) * lda + k0 + c4 * 4];
            As[c4 * 4 + 0][row] = v.x;
            As[c4 * 4 + 1][row] = v.y;
            As[c4 * 4 + 2][row] = v.z;
            As[c4 * 4 + 3][row] = v.w;
        }
        // Load W tile (BN x BK) -> Bs[k][n]
        constexpr int B_LD4 = BN * BK / 4;
        #pragma unroll
        for (int i = tid; i < B_LD4; i += THREADS) {
            int row = i / (BK / 4);
            int c4  = i % (BK / 4);
            float4 v = *(const float4*)&W[(size_t)(n0 + row) * K + k0 + c4 * 4];
            Bs[c4 * 4 + 0][row] = v.x;
            Bs[c4 * 4 + 1][row] = v.y;
            Bs[c4 * 4 + 2][row] = v.z;
            Bs[c4 * 4 + 3][row] = v.w;
        }
        __syncthreads();

        #pragma unroll
        for (int k = 0; k < BK; k++) {
            #pragma unroll
            for (int i = 0; i < TM / 4; i++)
                *(float4*)&ar[i * 4] = *(const float4*)&As[k][ty * TM + i * 4];
            #pragma unroll
            for (int j = 0; j < TN / 4; j++)
                *(float4*)&br[j * 4] = *(const float4*)&Bs[k][tx * TN + j * 4];
            #pragma unroll
            for (int i = 0; i < TM; i++)
                #pragma unroll
                for (int j = 0; j < TN; j++)
                    acc[i][j] = fmaf(ar[i], br[j], acc[i][j]);
        }
        __syncthreads();
    }

    #pragma unroll
    for (int i = 0; i < TM; i++) {
        int m = m0 + ty * TM + i;
        #pragma unroll
        for (int j = 0; j < TN; j++) {
            int n = n0 + tx * TN + j;
            float v = acc[i][j];
            if (ACT == 1) {
                v += bias[n];
                v = (v > 20.f) ? v : log1pf(expf(v));
            }
            C[(size_t)m * N + n] = v;
        }
    }
}

// ---------------- Causal depthwise conv (DC=4) + bias + silu ----------------
__global__ void conv_silu_kernel(const float* __restrict__ cw,    // [DI, DC]
                                 const float* __restrict__ cb) {  // [DI]
    int idx = blockIdx.x * blockDim.x + threadIdx.x;
    if (idx >= MROWS * DI) return;
    int d = idx & (DI - 1);
    int bt = idx >> 10;         // / DI
    int t = bt & (TT - 1);
    int b = bt >> 10;           // / TT

    float acc = cb[d];
    #pragma unroll
    for (int k = 0; k < DC; k++) {
        int tt = t + k - (DC - 1);
        if (tt >= 0) {
            acc = fmaf(g_xz[((size_t)(b * TT + tt)) * (2 * DI) + d], cw[d * DC + k], acc);
        }
    }
    g_xc[idx] = silu_fast(acc);
}

// ---------------- Selective scan ----------------
// Grid: (DI/32, B), Block: 512 threads. Thread = (d within chunk of 32) x (n in 0..15).
__global__ void scan_kernel(const float* __restrict__ A_log, // [DI, NN]
                            const float* __restrict__ Dsk) { // [DI]
    int tid = threadIdx.x;
    int n = tid & 15;
    int d = blockIdx.x * 32 + (tid >> 4);
    int b = blockIdx.y;

    float a = -__expf(A_log[d * NN + n]);
    float dskip = Dsk[d];
    float h = 0.f;

    size_t base = (size_t)b * TT;
    for (int t = 0; t < TT; t++) {
        size_t bt = base + t;
        float dtv = g_dt[bt * DI + d];
        float xcv = g_xc[bt * DI + d];
        float Bv  = g_dbc[bt * 64 + 32 + n];
        float Cv  = g_dbc[bt * 64 + 48 + n];
        float dA  = __expf(dtv * a);
        h = fmaf(dA, h, dtv * Bv * xcv);
        float p = h * Cv;
        // reduce over 16-lane n-group
        p += __shfl_xor_sync(0xffffffffu, p, 1, 16);
        p += __shfl_xor_sync(0xffffffffu, p, 2, 16);
        p += __shfl_xor_sync(0xffffffffu, p, 4, 16);
        p += __shfl_xor_sync(0xffffffffu, p, 8, 16);
        if (n == 0) {
            float zv = g_xz[bt * (2 * DI) + DI + d];
            g_y[bt * DI + d] = (p + xcv * dskip) * silu_fast(zv);
        }
    }
}

// ---------------- LayerNorm + residual (row = 512) ----------------
__global__ void ln_res_kernel(const float* __restrict__ g,
                              const float* __restrict__ bb) {
    __shared__ float red[8];
    int row = blockIdx.x;
    int tid = threadIdx.x;   // 256
    const float* r = g_out + (size_t)row * DD;
    float v0 = r[tid], v1 = r[tid + 256];

    float s = block_sum<8>(v0 + v1, red);
    float mu = s * (1.0f / DD);
    float d0 = v0 - mu, d1 = v1 - mu;
    float s2 = block_sum<8>(d0 * d0 + d1 * d1, red);
    float inv = rsqrtf(s2 * (1.0f / DD) + EPSV);

    size_t o = (size_t)row * DD;
    g_x[o + tid]       = d0 * inv * g[tid] + bb[tid] + g_x[o + tid];
    g_x[o + tid + 256] = d1 * inv * g[tid + 256] + bb[tid + 256] + g_x[o + tid + 256];
}

// ---------------- Attention pooling: scores -> softmax(T) -> weighted sum ----------------
__global__ void pool_kernel(const float* __restrict__ attn_w, // [D]
                            const float* __restrict__ attn_b) { // [1]
    __shared__ float sc[TT];
    __shared__ float red[16];
    int b = blockIdx.x;
    int tid = threadIdx.x;   // 512 = 16 warps
    int warp = tid >> 5, lane = tid & 31;

    // scores
    for (int t = warp; t < TT; t += 16) {
        const float* row = g_x + ((size_t)b * TT + t) * DD;
        float s = 0.f;
        for (int k = lane; k < DD; k += 32) s = fmaf(row[k], attn_w[k], s);
        #pragma unroll
        for (int o = 16; o; o >>= 1) s += __shfl_xor_sync(0xffffffffu, s, o);
        if (lane == 0) sc[t] = s + attn_b[0];
    }
    __syncthreads();

    // softmax over T
    float m = -1e30f;
    for (int t = tid; t < TT; t += 512) m = fmaxf(m, sc[t]);
    m = block_max<16>(m, red);
    float es = 0.f;
    for (int t = tid; t < TT; t += 512) {
        float e = __expf(sc[t] - m);
        sc[t] = e;
        es += e;
    }
    es = block_sum<16>(es, red);
    float inv = 1.0f / es;
    __syncthreads();

    // pooled
    for (int d = tid; d < DD; d += 512) {
        float acc = 0.f;
        const float* xp = g_x + (size_t)b * TT * DD + d;
        #pragma unroll 4
        for (int t = 0; t < TT; t++) acc = fmaf(sc[t], xp[(size_t)t * DD], acc);
        g_pooled[b * DD + d] = acc * inv;
    }
}

// ---------------- MLP head: 512->128 (LN,gelu) ->128 (LN,gelu) ->1 ----------------
__device__ __forceinline__ float gelu_exact(float v) {
    return 0.5f * v * (1.0f + erff(v * 0.70710678118654752f));
}

__global__ void head_kernel(const float* __restrict__ h1_w, const float* __restrict__ h1_b,
                            const float* __restrict__ ln1_g, const float* __restrict__ ln1_b,
                            const float* __restrict__ h2_w, const float* __restrict__ h2_b,
                            const float* __restrict__ ln2_g, const float* __restrict__ ln2_b,
                            const float* __restrict__ h3_w, const float* __restrict__ h3_b,
                            float* __restrict__ out) {
    __shared__ float sp[DD];
    __shared__ float sh[HH];
    __shared__ float red[4];
    int b = blockIdx.x;
    int i = threadIdx.x;  // 128

    for (int k = i; k < DD; k += HH) sp[k] = g_pooled[b * DD + k];
    __syncthreads();

    // layer 1
    float v = h1_b[i];
    const float* w1 = h1_w + (size_t)i * DD;
    for (int k = 0; k < DD; k++) v = fmaf(sp[k], w1[k], v);
    float mu = block_sum<4>(v, red) * (1.0f / HH);
    float dv = v - mu;
    float var = block_sum<4>(dv * dv, red) * (1.0f / HH);
    v = gelu_exact(dv * rsqrtf(var + EPSV) * ln1_g[i] + ln1_b[i]);
    sh[i] = v;
    __syncthreads();

    // layer 2
    float v2 = h2_b[i];
    const float* w2 = h2_w + (size_t)i * HH;
    for (int k = 0; k < HH; k++) v2 = fmaf(sh[k], w2[k], v2);
    mu = block_sum<4>(v2, red) * (1.0f / HH);
    float dv2 = v2 - mu;
    var = block_sum<4>(dv2 * dv2, red) * (1.0f / HH);
    v2 = gelu_exact(dv2 * rsqrtf(var + EPSV) * ln2_g[i] + ln2_b[i]);

    // layer 3
    float part = v2 * h3_w[i];
    float s = block_sum<4>(part, red);
    if (i == 0) out[b] = s + h3_b[0];
}

// ---------------- Launch ----------------
extern "C" void kernel_launch(void* const* d_in, const int* in_sizes, int n_in,
                              void* d_out, int out_size) {
    const float* ds     = (const float*)d_in[0];
    const float* in_w   = (const float*)d_in[1];
    const float* conv_w = (const float*)d_in[2];
    const float* conv_b = (const float*)d_in[3];
    const float* xp_w   = (const float*)d_in[4];
    const float* dt_w   = (const float*)d_in[5];
    const float* dt_b   = (const float*)d_in[6];
    const float* A_log  = (const float*)d_in[7];
    const float* D_sk   = (const float*)d_in[8];
    const float* out_w  = (const float*)d_in[9];
    const float* ln_g   = (const float*)d_in[10];
    const float* ln_b   = (const float*)d_in[11];
    const float* attn_w = (const float*)d_in[12];
    const float* attn_b = (const float*)d_in[13];
    const float* h1_w   = (const float*)d_in[14];
    const float* h1_b   = (const float*)d_in[15];
    const float* ln1_g  = (const float*)d_in[16];
    const float* ln1_b  = (const float*)d_in[17];
    const float* h2_w   = (const float*)d_in[18];
    const float* h2_b   = (const float*)d_in[19];
    const float* ln2_g  = (const float*)d_in[20];
    const float* ln2_b  = (const float*)d_in[21];
    const float* h3_w   = (const float*)d_in[22];
    const float* h3_b   = (const float*)d_in[23];
    float* out = (float*)d_out;

    // x <- input
    copy_kernel<<<(MROWS * DD + 255) / 256, 256>>>(ds, MROWS * DD);

    // device pointers to scratch, taken from a dummy launch-free path:
    // kernels reference the globals directly; GEMM needs raw pointers, which
    // we obtain per-kernel via small wrappers below using the globals' device
    // linkage. For gemm_tn we pass addresses computed on device side via
    // cudaGetSymbolAddress-free trick: declare extern refs. Simplest: use
    // separate __global__ entry points that forward the global pointers.
    // Instead, we just pass the globals through constant kernel params by
    // taking their device addresses at module scope:
    static float* px   = nullptr;
    static float* pxz  = nullptr;
    static float* pxc  = nullptr;
    static float* pdbc = nullptr;
    static float* pdt  = nullptr;
    static float* py   = nullptr;
    static float* pout = nullptr;
    if (!px) {  // one-time, outside capture semantics concerns (pure host lookups)
        cudaGetSymbolAddress((void**)&px,   g_x);
        cudaGetSymbolAddress((void**)&pxz,  g_xz);
        cudaGetSymbolAddress((void**)&pxc,  g_xc);
        cudaGetSymbolAddress((void**)&pdbc, g_dbc);
        cudaGetSymbolAddress((void**)&pdt,  g_dt);
        cudaGetSymbolAddress((void**)&py,   g_y);
        cudaGetSymbolAddress((void**)&pout, g_out);
    }

    for (int l = 0; l < LL; l++) {
        const float* inw  = in_w   + (size_t)l * (2 * DI) * DD;   // [2048, 512]
        const float* cw   = conv_w + (size_t)l * DI * DC;
        const float* cb   = conv_b + (size_t)l * DI;
        const float* xpw  = xp_w   + (size_t)l * 64 * DI;         // [64, 1024]
        const float* dtw  = dt_w   + (size_t)l * DI * DTR;        // [1024, 32]
        const float* dtb  = dt_b   + (size_t)l * DI;
        const float* al   = A_log  + (size_t)l * DI * NN;
        const float* dsk  = D_sk   + (size_t)l * DI;
        const float* ow   = out_w  + (size_t)l * DD * DI;         // [512, 1024]
        const float* lg   = ln_g   + (size_t)l * DD;
        const float* lb   = ln_b   + (size_t)l * DD;

        // in_proj: [4096,512] x [2048,512]^T -> [4096,2048]
        gemm_tn<128, 128, 16, 8, 8, 0><<<dim3(2 * DI / 128, MROWS / 128), 256>>>(
            px, DD, inw, nullptr, pxz, MROWS, 2 * DI, DD);

        // conv + silu
        conv_silu_kernel<<<(MROWS * DI + 255) / 256, 256>>>(cw, cb);

        // x_proj: [4096,1024] x [64,1024]^T -> [4096,64]
        gemm_tn<64, 64, 16, 4, 4, 0><<<dim3(1, MROWS / 64), 256>>>(
            pxc, DI, xpw, nullptr, pdbc, MROWS, 64, DI);

        // dt_proj + softplus: [4096,32(lda 64)] x [1024,32]^T -> [4096,1024]
        gemm_tn<128, 128, 16, 8, 8, 1><<<dim3(DI / 128, MROWS / 128), 256>>>(
            pdbc, 64, dtw, dtb, pdt, MROWS, DI, DTR);

        // selective scan (+ D skip + silu(z) gate)
        scan_kernel<<<dim3(DI / 32, BB), 512>>>(al, dsk);

        // out_proj: [4096,1024] x [512,1024]^T -> [4096,512]
        gemm_tn<128, 128, 16, 8, 8, 0><<<dim3(DD / 128, MROWS / 128), 256>>>(
            py, DI, ow, nullptr, pout, MROWS, DD, DI);

        // LN + residual -> x
        ln_res_kernel<<<MROWS, 256>>>(lg, lb);
    }

    // attention pooling
    pool_kernel<<<BB, 512>>>(attn_w, attn_b);

    // MLP head
    head_kernel<<<BB, HH>>>(h1_w, h1_b, ln1_g, ln1_b,
                            h2_w, h2_b, ln2_g, ln2_b, h3_w, h3_b, out);
}

// round 4
// speedup vs baseline: 1.1910x; 1.1910x over previous
#include <cuda_runtime.h>
#include <cuda_bf16.h>
#include <math.h>
#include <cstdint>

// ---------------- Problem constants ----------------
#define BB 4
#define TT 1024
#define DD 512
#define LL 4
#define NN 16
#define DC 4
#define DI 1024
#define DTR 32
#define HH 128
#define EPSV 1e-5f

#define MROWS (BB*TT)   // 4096

// ---------------- Scratch (device globals; no allocs allowed) ----------------
__device__ float g_x[MROWS * DD];        // running residual stream x
__device__ float g_xz[MROWS * 2 * DI];   // in_proj output (x_in | z)
__device__ float g_xc[MROWS * DI];       // conv+silu output
__device__ float g_dbc[MROWS * 64];      // x_proj output (dt_r | B | C)
__device__ float g_dt[MROWS * DI];       // softplus(dt)
__device__ float g_y[MROWS * DI];        // scan output (gated)
__device__ float g_out[MROWS * DD];      // out_proj output
__device__ float g_pooled[BB * DD];      // attention-pooled

// ---------------- helpers ----------------
__device__ __forceinline__ float silu_fast(float a) {
    return a * (1.0f / (1.0f + __expf(-a)));
}

// pack two fp32 into bf16x2 (lower16 = x, upper16 = y) + residual pack
__device__ __forceinline__ void split_pair(float x, float y, uint32_t& hi, uint32_t& lo) {
    uint32_t h;
    asm("cvt.rn.bf16x2.f32 %0, %1, %2;" : "=r"(h) : "f"(y), "f"(x));
    float fx = __uint_as_float(h << 16);
    float fy = __uint_as_float(h & 0xFFFF0000u);
    float lx = x - fx, ly = y - fy;
    uint32_t l;
    asm("cvt.rn.bf16x2.f32 %0, %1, %2;" : "=r"(l) : "f"(ly), "f"(lx));
    hi = h; lo = l;
}

__device__ __forceinline__ void mma16816(float* c, const uint32_t* a, const uint32_t* b) {
    asm("mma.sync.aligned.m16n8k16.row.col.f32.bf16.bf16.f32 "
        "{%0,%1,%2,%3}, {%4,%5,%6,%7}, {%8,%9}, {%0,%1,%2,%3};"
        : "+f"(c[0]), "+f"(c[1]), "+f"(c[2]), "+f"(c[3])
        : "r"(a[0]), "r"(a[1]), "r"(a[2]), "r"(a[3]), "r"(b[0]), "r"(b[1]));
}

// ---------------- Tensor-core GEMM (3xBF16 split): C[M,N] = A[M,K(lda)] @ W[N,K]^T ----------------
// BM=128 fixed, BK=32 fixed, 256 threads (8 warps = WARPS_M x WARPS_N).
// ACT: 0 = none, 1 = softplus(acc + bias[n])
template<int BN, int WARPS_M, int WARPS_N, int ACT>
__global__ void __launch_bounds__(256)
gemm_mma(const float* __restrict__ A, int lda,
         const float* __restrict__ W,
         const float* __restrict__ bias,
         float* __restrict__ C, int N, int K) {
    constexpr int BM = 128, BK = 32, SK = 34;   // SK: padded k stride (bf16 elems)
    constexpr int WM = BM / WARPS_M, WN = BN / WARPS_N;
    constexpr int MT = WM / 16, NT = WN / 8;

    __shared__ __align__(16) uint16_t sAh[BM * SK], sAl[BM * SK];
    __shared__ __align__(16) uint16_t sBh[BN * SK], sBl[BN * SK];

    const int tid = threadIdx.x;
    const int wid = tid >> 5, lane = tid & 31;
    const int gq = lane >> 2;    // group row (0..7)
    const int q  = lane & 3;     // group col (0..3)
    const int wm = wid % WARPS_M, wn = wid / WARPS_M;
    const int m0 = blockIdx.y * BM;
    const int n0 = blockIdx.x * BN;

    float acc[MT][NT][4];
    #pragma unroll
    for (int i = 0; i < MT; i++)
        #pragma unroll
        for (int j = 0; j < NT; j++)
            #pragma unroll
            for (int v = 0; v < 4; v++) acc[i][j][v] = 0.f;

    // loader mappings
    const int arow = tid >> 1, aks = (tid & 1) * 16;      // A: 2 threads/row, 16 k each
    constexpr int TPR = 256 / BN;                          // B threads per row
    const int brow = tid / TPR, bks = (tid % TPR) * (BK / TPR);

    for (int k0 = 0; k0 < K; k0 += BK) {
        // ---- load + convert A tile (128 x 32) ----
        {
            const float* ap = A + (size_t)(m0 + arow) * lda + k0 + aks;
            uint32_t* dh = (uint32_t*)&sAh[arow * SK + aks];
            uint32_t* dl = (uint32_t*)&sAl[arow * SK + aks];
            #pragma unroll
            for (int j = 0; j < 16; j += 4) {
                float4 v = *(const float4*)(ap + j);
                uint32_t h0, l0, h1, l1;
                split_pair(v.x, v.y, h0, l0);
                split_pair(v.z, v.w, h1, l1);
                dh[j / 2] = h0; dh[j / 2 + 1] = h1;
                dl[j / 2] = l0; dl[j / 2 + 1] = l1;
            }
        }
        // ---- load + convert B tile (BN x 32) ----
        {
            const float* wp = W + (size_t)(n0 + brow) * K + k0 + bks;
            uint32_t* dh = (uint32_t*)&sBh[brow * SK + bks];
            uint32_t* dl = (uint32_t*)&sBl[brow * SK + bks];
            #pragma unroll
            for (int j = 0; j < BK / TPR; j += 4) {
                float4 v = *(const float4*)(wp + j);
                uint32_t h0, l0, h1, l1;
                split_pair(v.x, v.y, h0, l0);
                split_pair(v.z, v.w, h1, l1);
                dh[j / 2] = h0; dh[j / 2 + 1] = h1;
                dl[j / 2] = l0; dl[j / 2 + 1] = l1;
            }
        }
        __syncthreads();

        #pragma unroll
        for (int kk = 0; kk < 2; kk++) {
            const int kb = kk * 16;
            // B fragments for this warp
            uint32_t bh[NT][2], bl[NT][2];
            #pragma unroll
            for (int nt = 0; nt < NT; nt++) {
                int n = wn * WN + nt * 8 + gq;
                int o = n * SK + kb + q * 2;
                bh[nt][0] = *(const uint32_t*)&sBh[o];
                bh[nt][1] = *(const uint32_t*)&sBh[o + 8];
                bl[nt][0] = *(const uint32_t*)&sBl[o];
                bl[nt][1] = *(const uint32_t*)&sBl[o + 8];
            }
            #pragma unroll
            for (int mt = 0; mt < MT; mt++) {
                int r = wm * WM + mt * 16 + gq;
                int o = r * SK + kb + q * 2;
                uint32_t ah[4], al[4];
                ah[0] = *(const uint32_t*)&sAh[o];
                ah[1] = *(const uint32_t*)&sAh[o + 8 * SK];
                ah[2] = *(const uint32_t*)&sAh[o + 8];
                ah[3] = *(const uint32_t*)&sAh[o + 8 * SK + 8];
                al[0] = *(const uint32_t*)&sAl[o];
                al[1] = *(const uint32_t*)&sAl[o + 8 * SK];
                al[2] = *(const uint32_t*)&sAl[o + 8];
                al[3] = *(const uint32_t*)&sAl[o + 8 * SK + 8];
                #pragma unroll
                for (int nt = 0; nt < NT; nt++) {
                    mma16816(acc[mt][nt], ah, bh[nt]);   // hi * hi
                    mma16816(acc[mt][nt], ah, bl[nt]);   // hi * lo
                    mma16816(acc[mt][nt], al, bh[nt]);   // lo * hi
                }
            }
        }
        __syncthreads();
    }

    // ---- epilogue ----
    #pragma unroll
    for (int mt = 0; mt < MT; mt++) {
        int r = m0 + wm * WM + mt * 16 + gq;
        #pragma unroll
        for (int nt = 0; nt < NT; nt++) {
            int c = n0 + wn * WN + nt * 8 + q * 2;
            float x0 = acc[mt][nt][0], x1 = acc[mt][nt][1];
            float x2 = acc[mt][nt][2], x3 = acc[mt][nt][3];
            if (ACT == 1) {
                float b0 = bias[c], b1 = bias[c + 1];
                x0 += b0; x1 += b1; x2 += b0; x3 += b1;
                x0 = (x0 > 20.f) ? x0 : log1pf(expf(x0));
                x1 = (x1 > 20.f) ? x1 : log1pf(expf(x1));
                x2 = (x2 > 20.f) ? x2 : log1pf(expf(x2));
                x3 = (x3 > 20.f) ? x3 : log1pf(expf(x3));
            }
            *(float2*)&C[(size_t)r * N + c]       = make_float2(x0, x1);
            *(float2*)&C[(size_t)(r + 8) * N + c] = make_float2(x2, x3);
        }
    }
}

// ---------------- Block reduce helpers ----------------
template<int WARPS>
__device__ __forceinline__ float block_sum(float v, float* red) {
    #pragma unroll
    for (int o = 16; o; o >>= 1) v += __shfl_xor_sync(0xffffffffu, v, o);
    int w = threadIdx.x >> 5;
    if ((threadIdx.x & 31) == 0) red[w] = v;
    __syncthreads();
    float s = 0.f;
    #pragma unroll
    for (int i = 0; i < WARPS; i++) s += red[i];
    __syncthreads();
    return s;
}

template<int WARPS>
__device__ __forceinline__ float block_max(float v, float* red) {
    #pragma unroll
    for (int o = 16; o; o >>= 1) v = fmaxf(v, __shfl_xor_sync(0xffffffffu, v, o));
    int w = threadIdx.x >> 5;
    if ((threadIdx.x & 31) == 0) red[w] = v;
    __syncthreads();
    float s = -1e30f;
    #pragma unroll
    for (int i = 0; i < WARPS; i++) s = fmaxf(s, red[i]);
    __syncthreads();
    return s;
}

// ---------------- Copy input into residual stream ----------------
__global__ void copy_kernel(const float* __restrict__ src, int n) {
    int i = blockIdx.x * blockDim.x + threadIdx.x;
    if (i < n) g_x[i] = src[i];
}

// ---------------- Causal depthwise conv (DC=4) + bias + silu ----------------
__global__ void conv_silu_kernel(const float* __restrict__ cw,    // [DI, DC]
                                 const float* __restrict__ cb) {  // [DI]
    int idx = blockIdx.x * blockDim.x + threadIdx.x;
    if (idx >= MROWS * DI) return;
    int d = idx & (DI - 1);
    int bt = idx >> 10;
    int t = bt & (TT - 1);
    int b = bt >> 10;

    float acc = cb[d];
    #pragma unroll
    for (int k = 0; k < DC; k++) {
        int tt = t + k - (DC - 1);
        if (tt >= 0) {
            acc = fmaf(g_xz[((size_t)(b * TT + tt)) * (2 * DI) + d], cw[d * DC + k], acc);
        }
    }
    g_xc[idx] = silu_fast(acc);
}

// ---------------- Selective scan ----------------
__global__ void scan_kernel(const float* __restrict__ A_log, // [DI, NN]
                            const float* __restrict__ Dsk) { // [DI]
    int tid = threadIdx.x;
    int n = tid & 15;
    int d = blockIdx.x * 32 + (tid >> 4);
    int b = blockIdx.y;

    float a = -__expf(A_log[d * NN + n]);
    float dskip = Dsk[d];
    float h = 0.f;

    size_t base = (size_t)b * TT;
    for (int t = 0; t < TT; t++) {
        size_t bt = base + t;
        float dtv = g_dt[bt * DI + d];
        float xcv = g_xc[bt * DI + d];
        float Bv  = g_dbc[bt * 64 + 32 + n];
        float Cv  = g_dbc[bt * 64 + 48 + n];
        float dA  = __expf(dtv * a);
        h = fmaf(dA, h, dtv * Bv * xcv);
        float p = h * Cv;
        p += __shfl_xor_sync(0xffffffffu, p, 1, 16);
        p += __shfl_xor_sync(0xffffffffu, p, 2, 16);
        p += __shfl_xor_sync(0xffffffffu, p, 4, 16);
        p += __shfl_xor_sync(0xffffffffu, p, 8, 16);
        if (n == 0) {
            float zv = g_xz[bt * (2 * DI) + DI + d];
            g_y[bt * DI + d] = (p + xcv * dskip) * silu_fast(zv);
        }
    }
}

// ---------------- LayerNorm + residual ----------------
__global__ void ln_res_kernel(const float* __restrict__ g,
                              const float* __restrict__ bb) {
    __shared__ float red[8];
    int row = blockIdx.x;
    int tid = threadIdx.x;   // 256
    const float* r = g_out + (size_t)row * DD;
    float v0 = r[tid], v1 = r[tid + 256];

    float s = block_sum<8>(v0 + v1, red);
    float mu = s * (1.0f / DD);
    float d0 = v0 - mu, d1 = v1 - mu;
    float s2 = block_sum<8>(d0 * d0 + d1 * d1, red);
    float inv = rsqrtf(s2 * (1.0f / DD) + EPSV);

    size_t o = (size_t)row * DD;
    g_x[o + tid]       = d0 * inv * g[tid] + bb[tid] + g_x[o + tid];
    g_x[o + tid + 256] = d1 * inv * g[tid + 256] + bb[tid + 256] + g_x[o + tid + 256];
}

// ---------------- Attention pooling ----------------
__global__ void pool_kernel(const float* __restrict__ attn_w,
                            const float* __restrict__ attn_b) {
    __shared__ float sc[TT];
    __shared__ float red[16];
    int b = blockIdx.x;
    int tid = threadIdx.x;   // 512 = 16 warps
    int warp = tid >> 5, lane = tid & 31;

    for (int t = warp; t < TT; t += 16) {
        const float* row = g_x + ((size_t)b * TT + t) * DD;
        float s = 0.f;
        for (int k = lane; k < DD; k += 32) s = fmaf(row[k], attn_w[k], s);
        #pragma unroll
        for (int o = 16; o; o >>= 1) s += __shfl_xor_sync(0xffffffffu, s, o);
        if (lane == 0) sc[t] = s + attn_b[0];
    }
    __syncthreads();

    float m = -1e30f;
    for (int t = tid; t < TT; t += 512) m = fmaxf(m, sc[t]);
    m = block_max<16>(m, red);
    float es = 0.f;
    for (int t = tid; t < TT; t += 512) {
        float e = __expf(sc[t] - m);
        sc[t] = e;
        es += e;
    }
    es = block_sum<16>(es, red);
    float inv = 1.0f / es;
    __syncthreads();

    for (int d = tid; d < DD; d += 512) {
        float acc = 0.f;
        const float* xp = g_x + (size_t)b * TT * DD + d;
        #pragma unroll 4
        for (int t = 0; t < TT; t++) acc = fmaf(sc[t], xp[(size_t)t * DD], acc);
        g_pooled[b * DD + d] = acc * inv;
    }
}

// ---------------- MLP head ----------------
__device__ __forceinline__ float gelu_exact(float v) {
    return 0.5f * v * (1.0f + erff(v * 0.70710678118654752f));
}

__global__ void head_kernel(const float* __restrict__ h1_w, const float* __restrict__ h1_b,
                            const float* __restrict__ ln1_g, const float* __restrict__ ln1_b,
                            const float* __restrict__ h2_w, const float* __restrict__ h2_b,
                            const float* __restrict__ ln2_g, const float* __restrict__ ln2_b,
                            const float* __restrict__ h3_w, const float* __restrict__ h3_b,
                            float* __restrict__ out) {
    __shared__ float sp[DD];
    __shared__ float sh[HH];
    __shared__ float red[4];
    int b = blockIdx.x;
    int i = threadIdx.x;  // 128

    for (int k = i; k < DD; k += HH) sp[k] = g_pooled[b * DD + k];
    __syncthreads();

    float v = h1_b[i];
    const float* w1 = h1_w + (size_t)i * DD;
    for (int k = 0; k < DD; k++) v = fmaf(sp[k], w1[k], v);
    float mu = block_sum<4>(v, red) * (1.0f / HH);
    float dv = v - mu;
    float var = block_sum<4>(dv * dv, red) * (1.0f / HH);
    v = gelu_exact(dv * rsqrtf(var + EPSV) * ln1_g[i] + ln1_b[i]);
    sh[i] = v;
    __syncthreads();

    float v2 = h2_b[i];
    const float* w2 = h2_w + (size_t)i * HH;
    for (int k = 0; k < HH; k++) v2 = fmaf(sh[k], w2[k], v2);
    mu = block_sum<4>(v2, red) * (1.0f / HH);
    float dv2 = v2 - mu;
    var = block_sum<4>(dv2 * dv2, red) * (1.0f / HH);
    v2 = gelu_exact(dv2 * rsqrtf(var + EPSV) * ln2_g[i] + ln2_b[i]);

    float part = v2 * h3_w[i];
    float s = block_sum<4>(part, red);
    if (i == 0) out[b] = s + h3_b[0];
}

// ---------------- Launch ----------------
extern "C" void kernel_launch(void* const* d_in, const int* in_sizes, int n_in,
                              void* d_out, int out_size) {
    const float* ds     = (const float*)d_in[0];
    const float* in_w   = (const float*)d_in[1];
    const float* conv_w = (const float*)d_in[2];
    const float* conv_b = (const float*)d_in[3];
    const float* xp_w   = (const float*)d_in[4];
    const float* dt_w   = (const float*)d_in[5];
    const float* dt_b   = (const float*)d_in[6];
    const float* A_log  = (const float*)d_in[7];
    const float* D_sk   = (const float*)d_in[8];
    const float* out_w  = (const float*)d_in[9];
    const float* ln_g   = (const float*)d_in[10];
    const float* ln_b   = (const float*)d_in[11];
    const float* attn_w = (const float*)d_in[12];
    const float* attn_b = (const float*)d_in[13];
    const float* h1_w   = (const float*)d_in[14];
    const float* h1_b   = (const float*)d_in[15];
    const float* ln1_g  = (const float*)d_in[16];
    const float* ln1_b  = (const float*)d_in[17];
    const float* h2_w   = (const float*)d_in[18];
    const float* h2_b   = (const float*)d_in[19];
    const float* ln2_g  = (const float*)d_in[20];
    const float* ln2_b  = (const float*)d_in[21];
    const float* h3_w   = (const float*)d_in[22];
    const float* h3_b   = (const float*)d_in[23];
    float* out = (float*)d_out;

    static float* px   = nullptr;
    static float* pxz  = nullptr;
    static float* pxc  = nullptr;
    static float* pdbc = nullptr;
    static float* pdt  = nullptr;
    static float* py   = nullptr;
    static float* pout = nullptr;
    if (!px) {  // one-time host-side setup (first call is the non-captured correctness run)
        cudaGetSymbolAddress((void**)&px,   g_x);
        cudaGetSymbolAddress((void**)&pxz,  g_xz);
        cudaGetSymbolAddress((void**)&pxc,  g_xc);
        cudaGetSymbolAddress((void**)&pdbc, g_dbc);
        cudaGetSymbolAddress((void**)&pdt,  g_dt);
        cudaGetSymbolAddress((void**)&py,   g_y);
        cudaGetSymbolAddress((void**)&pout, g_out);
    }

    // x <- input
    copy_kernel<<<(MROWS * DD + 255) / 256, 256>>>(ds, MROWS * DD);

    for (int l = 0; l < LL; l++) {
        const float* inw  = in_w   + (size_t)l * (2 * DI) * DD;   // [2048, 512]
        const float* cw   = conv_w + (size_t)l * DI * DC;
        const float* cb   = conv_b + (size_t)l * DI;
        const float* xpw  = xp_w   + (size_t)l * 64 * DI;         // [64, 1024]
        const float* dtw  = dt_w   + (size_t)l * DI * DTR;        // [1024, 32]
        const float* dtb  = dt_b   + (size_t)l * DI;
        const float* al   = A_log  + (size_t)l * DI * NN;
        const float* dsk  = D_sk   + (size_t)l * DI;
        const float* ow   = out_w  + (size_t)l * DD * DI;         // [512, 1024]
        const float* lg   = ln_g   + (size_t)l * DD;
        const float* lb   = ln_b   + (size_t)l * DD;

        // in_proj: [4096,512] x [2048,512]^T -> [4096,2048]   (mma bf16 3x)
        gemm_mma<128, 2, 4, 0><<<dim3(2 * DI / 128, MROWS / 128), 256>>>(
            px, DD, inw, nullptr, pxz, 2 * DI, DD);

        // conv + silu
        conv_silu_kernel<<<(MROWS * DI + 255) / 256, 256>>>(cw, cb);

        // x_proj: [4096,1024] x [64,1024]^T -> [4096,64]   (mma bf16 3x)
        gemm_mma<64, 4, 2, 0><<<dim3(1, MROWS / 128), 256>>>(
            pxc, DI, xpw, nullptr, pdbc, 64, DI);

        // dt_proj + softplus: [4096,32(lda 64)] x [1024,32]^T -> [4096,1024]  (mma bf16 3x)
        gemm_mma<128, 2, 4, 1><<<dim3(DI / 128, MROWS / 128), 256>>>(
            pdbc, 64, dtw, dtb, pdt, DI, DTR);

        // selective scan (+ D skip + silu(z) gate)
        scan_kernel<<<dim3(DI / 32, BB), 512>>>(al, dsk);

        // out_proj: [4096,1024] x [512,1024]^T -> [4096,512]   (mma bf16 3x)
        gemm_mma<128, 2, 4, 0><<<dim3(DD / 128, MROWS / 128), 256>>>(
            py, DI, ow, nullptr, pout, DD, DI);

        // LN + residual -> x
        ln_res_kernel<<<MROWS, 256>>>(lg, lb);
    }

    // attention pooling
    pool_kernel<<<BB, 512>>>(attn_w, attn_b);

    // MLP head
    head_kernel<<<BB, HH>>>(h1_w, h1_b, ln1_g, ln1_b,
                            h2_w, h2_b, ln2_g, ln2_b, h3_w, h3_b, out);
}